// round 4
// baseline (speedup 1.0000x reference)
#include <cuda_runtime.h>
#include <math.h>

#define BT   128     // threads per block: 4 warps, each point served by a warp quad
#define PT   32      // points per block
#define NCH  101     // 100 SH channels + 1 time index
#define LMAX 10

// (-1)^m * (2m-1)!!  (compile-time)
__host__ __device__ constexpr double neg_dfact(int m) {
    double r = 1.0;
    for (int k = 1; k <= m; k++) r *= (double)(-(2 * k - 1));
    return r;
}

// s^M, unrolled at compile time
template <int M>
__device__ __forceinline__ float powS(float s) {
    float r = 1.0f;
    #pragma unroll
    for (int k = 0; k < M; k++) r *= s;
    return r;
}

// One full Legendre chain for order M: writes all Y_l^{±M}, l = M..LMAX-1.
template <int M>
__device__ __forceinline__ void chain(float x, float s, float c1, float s1,
                                      float* __restrict__ st,
                                      const float* __restrict__ sK) {
    // cos(M*phi), sin(M*phi) via unrolled angle-addition
    float cm = 1.0f, sm = 0.0f;
    #pragma unroll
    for (int k = 0; k < M; k++) {
        const float t = cm * c1 - sm * s1;
        sm = sm * c1 + cm * s1;
        cm = t;
    }

    float pmm = (float)neg_dfact(M) * powS<M>(s);

    float plm2 = pmm;                              // P[M][M]
    {
        const int l = M;
        const float Kc = sK[l * (l + 1) / 2 + M];
        if (M == 0) st[0] = Kc * plm2;
        else {
            st[l * l + l + M] = Kc * cm * plm2;
            st[l * l + l - M] = Kc * sm * plm2;
        }
    }
    if (M + 1 < LMAX) {
        float plm1 = x * (float)(2 * M + 1) * pmm; // P[M+1][M]
        {
            const int l = M + 1;
            const float Kc = sK[l * (l + 1) / 2 + M];
            if (M == 0) st[l * l + l] = Kc * plm1;
            else {
                st[l * l + l + M] = Kc * cm * plm1;
                st[l * l + l - M] = Kc * sm * plm1;
            }
        }
        #pragma unroll
        for (int l = M + 2; l < LMAX; l++) {
            const float pl = ((float)(2 * l - 1) * x * plm1
                              - (float)(l + M - 1) * plm2) * (1.0f / (float)(l - M));
            plm2 = plm1;
            plm1 = pl;
            const float Kc = sK[l * (l + 1) / 2 + M];
            if (M == 0) st[l * l + l] = Kc * pl;
            else {
                st[l * l + l + M] = Kc * cm * pl;
                st[l * l + l - M] = Kc * sm * pl;
            }
        }
    }
}

__global__ __launch_bounds__(BT, 16) void sh_kernel(const float* __restrict__ lonlat,
                                                    float* __restrict__ out,
                                                    int N) {
    __shared__ __align__(16) float stage[PT * NCH];
    __shared__ float sK[55];

    const int tid  = threadIdx.x;
    const int wid  = tid >> 5;     // 0..3 = quarter (chain group)
    const int lane = tid & 31;     // point within block

    // ---- normalization constants K(l,|m|), 55 entries (sqrt(2) folded for m>0) ----
    if (tid < 55) {
        int l = 0, tri = 0;
        while (tri + l + 1 <= tid) { tri += l + 1; l++; }
        int am = tid - tri;
        float ratio = 1.0f;                          // (l-am)! / (l+am)!
        for (int k = l - am + 1; k <= l + am; k++) ratio /= (float)k;
        float K = sqrtf((float)(2 * l + 1) * 0.07957747154594767f * ratio);
        if (am > 0) K *= 1.41421356237309515f;
        sK[tid] = K;
    }
    __syncthreads();

    const long long i = (long long)blockIdx.x * PT + lane;
    if (i < N) {
        const float lon = lonlat[i * 3 + 0];
        const float lat = lonlat[i * 3 + 1];

        const float D2R = 0.017453292519943295f;
        const float phi = (lon + 180.0f) * D2R;
        const float th  = (lat +  90.0f) * D2R;

        float s, x;                  // sin(theta), cos(theta)
        sincosf(th, &s, &x);
        float s1, c1;                // sin(phi), cos(phi)
        sincosf(phi, &s1, &c1);

        float* st = &stage[lane * NCH];
        if (wid == 0) {
            chain<0>(x, s, c1, s1, st, sK);
            chain<7>(x, s, c1, s1, st, sK);
            st[100] = lonlat[i * 3 + 2];             // time index
        } else if (wid == 1) {
            chain<1>(x, s, c1, s1, st, sK);
            chain<6>(x, s, c1, s1, st, sK);
        } else if (wid == 2) {
            chain<2>(x, s, c1, s1, st, sK);
            chain<5>(x, s, c1, s1, st, sK);
            chain<9>(x, s, c1, s1, st, sK);
        } else {
            chain<3>(x, s, c1, s1, st, sK);
            chain<4>(x, s, c1, s1, st, sK);
            chain<8>(x, s, c1, s1, st, sK);
        }
    }
    __syncthreads();

    // ---- coalesced streaming copy-out ----
    const long long blockBase = (long long)blockIdx.x * PT;
    long long rem = (long long)N - blockBase;
    const int nvalid = (rem >= PT) ? PT : (rem > 0 ? (int)rem : 0);

    if (nvalid == PT) {
        const float4* s4 = (const float4*)stage;
        float4* o4 = (float4*)(out + blockBase * NCH);
        #pragma unroll
        for (int j = tid; j < (PT * NCH) / 4; j += BT) {
            __stcs(&o4[j], s4[j]);
        }
    } else if (nvalid > 0) {
        const int tot = nvalid * NCH;
        float* o = out + blockBase * NCH;
        for (int j = tid; j < tot; j += BT) {
            __stcs(&o[j], stage[j]);
        }
    }
}

extern "C" void kernel_launch(void* const* d_in, const int* in_sizes, int n_in,
                              void* d_out, int out_size) {
    const float* lonlat = (const float*)d_in[0];
    const int N = in_sizes[0] / 3;
    float* out = (float*)d_out;
    const int nb = (N + PT - 1) / PT;
    sh_kernel<<<nb, BT>>>(lonlat, out, N);
}